// round 12
// baseline (speedup 1.0000x reference)
#include <cuda_runtime.h>
#include <math.h>
#include <mma.h>

using namespace nvcuda;

#define BB 8
#define TT 64
#define NN 256
#define HH 256
#define DI 6
#define DO 9
#define G3 (3*HH)   // 768

// ---------------- scratch (device globals; no runtime allocation) ----------------
__device__ __align__(16) float g_gx[(size_t)BB*TT*NN*G3];
__device__ __align__(16) float g_hseq[(size_t)BB*TT*NN*HH];
__device__ __align__(16) float g_Axseq[(size_t)BB*TT*NN*HH];
__device__ __align__(16) float g_h [BB*NN*HH];
__device__ __align__(16) float g_Ah[BB*NN*HH];
__device__ __align__(16) float g_z [BB*NN*HH];
__device__ __align__(16) float g_u [BB*NN*HH];
__device__ __align__(16) float g_Au[BB*NN*HH];
__device__ int   g_cnt[NN];
__device__ int   g_col[NN*NN];
__device__ float g_val[NN*NN];

__device__ __forceinline__ float sigmoidf_(float x){ return 1.0f / (1.0f + expf(-x)); }

typedef wmma::fragment<wmma::matrix_a, 16, 16, 8, wmma::precision::tf32, wmma::row_major> FragA;
typedef wmma::fragment<wmma::matrix_b, 16, 16, 8, wmma::precision::tf32, wmma::row_major> FragB;
typedef wmma::fragment<wmma::accumulator, 16, 16, 8, float> FragC;

__device__ __forceinline__ void cvt_tf32_a(FragA& f){
    #pragma unroll
    for (int i = 0; i < f.num_elements; i++) f.x[i] = wmma::__float_to_tf32(f.x[i]);
}
__device__ __forceinline__ void cvt_tf32_b(FragB& f){
    #pragma unroll
    for (int i = 0; i < f.num_elements; i++) f.x[i] = wmma::__float_to_tf32(f.x[i]);
}

// ---------------- CSR build from dense adjacency (zeros are exact) ----------------
__global__ void build_csr(const float* __restrict__ adj){
    int n = threadIdx.x;
    int c = 0;
    for (int m = 0; m < NN; m++){
        float v = adj[n*NN + m];
        if (v != 0.0f){ g_col[n*NN + c] = m; g_val[n*NN + c] = v; c++; }
    }
    g_cnt[n] = c;
}

__global__ void zero_h(){
    int i = blockIdx.x * 256 + threadIdx.x;
    g_h[i] = 0.0f;
}

// ---------------- layer-0 gx: per (b,t), gx = (A (x) (x*mask)) @ Wx0 + b0 ----------------
__global__ void prep_gx0(const float* __restrict__ x2d, const float* __restrict__ mask,
                         const float* __restrict__ Wx0, const float* __restrict__ b0){
    __shared__ float xm[NN*DI];
    __shared__ float ax[NN*DI];
    __shared__ float Ws[DI*G3];
    int bt = blockIdx.x;
    int tid = threadIdx.x;

    for (int i = tid; i < NN*DI; i += 256){
        int n = i / DI;
        xm[i] = x2d[(size_t)bt*NN*DI + i] * mask[(size_t)bt*NN + n];
    }
    for (int i = tid; i < DI*G3; i += 256) Ws[i] = Wx0[i];
    __syncthreads();

    {   // sparse conv: one node per thread
        int n = tid;
        float a0=0,a1=0,a2=0,a3=0,a4=0,a5=0;
        int cn = g_cnt[n];
        for (int e = 0; e < cn; e++){
            int m = g_col[n*NN + e];
            float w = g_val[n*NN + e];
            const float* xr = xm + m*DI;
            a0 += w*xr[0]; a1 += w*xr[1]; a2 += w*xr[2];
            a3 += w*xr[3]; a4 += w*xr[4]; a5 += w*xr[5];
        }
        float* ar = ax + n*DI;
        ar[0]=a0; ar[1]=a1; ar[2]=a2; ar[3]=a3; ar[4]=a4; ar[5]=a5;
    }
    __syncthreads();

    for (int jj = 0; jj < 3; jj++){
        int j = tid + (jj << 8);
        float w0=Ws[j], w1=Ws[G3+j], w2=Ws[2*G3+j], w3=Ws[3*G3+j], w4=Ws[4*G3+j], w5=Ws[5*G3+j];
        float bj = b0[j];
        float* gout = g_gx + (size_t)bt*NN*G3 + j;
        for (int n = 0; n < NN; n++){
            const float* axr = ax + n*DI;
            float s = bj + axr[0]*w0 + axr[1]*w1 + axr[2]*w2
                         + axr[3]*w3 + axr[4]*w4 + axr[5]*w5;
            gout[(size_t)n*G3] = s;
        }
    }
}

// ---------------- per-step sparse conv, float4-vectorized (R11-proven) ----------------
__global__ void __launch_bounds__(64,16) spconv_step(int which){
    const float* __restrict__ X = which ? g_u  : g_h;
    float* __restrict__       C = which ? g_Au : g_Ah;
    int n = blockIdx.x & 255;
    int q = blockIdx.x >> 8;
    int k4 = threadIdx.x;
    int cn = g_cnt[n];
    const int*   cp = g_col + n*NN;
    const float* vp = g_val + n*NN;
    const float4* Xb = (const float4*)(X + (size_t)q*NN*HH) + k4;
    float4 a0 = make_float4(0,0,0,0), a1 = a0, a2 = a0, a3 = a0;
    int e = 0;
    for (; e + 4 <= cn; e += 4){
        float w0 = vp[e],   w1 = vp[e+1], w2 = vp[e+2], w3 = vp[e+3];
        float4 x0 = Xb[(size_t)cp[e]   << 6];
        float4 x1 = Xb[(size_t)cp[e+1] << 6];
        float4 x2 = Xb[(size_t)cp[e+2] << 6];
        float4 x3 = Xb[(size_t)cp[e+3] << 6];
        a0.x += w0*x0.x; a0.y += w0*x0.y; a0.z += w0*x0.z; a0.w += w0*x0.w;
        a1.x += w1*x1.x; a1.y += w1*x1.y; a1.z += w1*x1.z; a1.w += w1*x1.w;
        a2.x += w2*x2.x; a2.y += w2*x2.y; a2.z += w2*x2.z; a2.w += w2*x2.w;
        a3.x += w3*x3.x; a3.y += w3*x3.y; a3.z += w3*x3.z; a3.w += w3*x3.w;
    }
    for (; e < cn; e++){
        float w = vp[e];
        float4 x = Xb[(size_t)cp[e] << 6];
        a0.x += w*x.x; a0.y += w*x.y; a0.z += w*x.z; a0.w += w*x.w;
    }
    float4 r;
    r.x = (a0.x + a1.x) + (a2.x + a3.x);
    r.y = (a0.y + a1.y) + (a2.y + a3.y);
    r.z = (a0.z + a1.z) + (a2.z + a3.z);
    r.w = (a0.w + a1.w) + (a2.w + a3.w);
    ((float4*)(C + (size_t)q*NN*HH + (n << 8)))[k4] = r;
}

// ---------------- sequence sparse conv (R1-proven): g_Axseq = A (x) g_hseq ----------------
__global__ void spconv_seq(){
    __shared__ float Xs[NN*32];
    int kh = blockIdx.x;       // 0..7
    int q  = blockIdx.y;       // 0..511
    int tid = threadIdx.x;
    const float4* X4 = (const float4*)g_hseq;
    float4* Xs4 = (float4*)Xs;
    for (int i = tid; i < NN*8; i += 256){
        int m = i >> 3, c4 = i & 7;
        Xs4[i] = X4[((size_t)q*NN + m)*64 + kh*8 + c4];
    }
    __syncthreads();
    int k  = tid & 31;
    int ng = tid >> 5;         // 0..7
    for (int nb = 0; nb < NN; nb += 8){
        int n = nb + ng;
        int cn = g_cnt[n];
        const int*   cp = g_col + n*NN;
        const float* vp = g_val + n*NN;
        float a0 = 0.0f, a1 = 0.0f;
        int e = 0;
        for (; e + 2 <= cn; e += 2){
            a0 += vp[e]   * Xs[(cp[e]   << 5) + k];
            a1 += vp[e+1] * Xs[(cp[e+1] << 5) + k];
        }
        if (e < cn) a0 += vp[e] * Xs[(cp[e] << 5) + k];
        g_Axseq[((size_t)q*NN + n)*HH + (kh << 5) + k] = a0 + a1;
    }
}

// ---------------- wmma tf32 64x64-tile GEMM core (8 warps, warp = 32x16) ----------------
// Computes Cs[64][72] = A[r0:r0+64, 0:256] @ B[0:256, j0:j0+64]; caller does epilogue.
__device__ __forceinline__ void mma_tile64(const float* __restrict__ Abase, int lda,
                                           const float* __restrict__ Bbase, int ldb,
                                           float* Cs){
    int w = threadIdx.x >> 5;
    int wr = w >> 2, wc = w & 3;           // warp tile: rows wr*32, cols wc*16
    FragC c0, c1;
    wmma::fill_fragment(c0, 0.0f);
    wmma::fill_fragment(c1, 0.0f);
    const float* Ap = Abase + (size_t)(wr*32)*lda;
    const float* Bp = Bbase + wc*16;
    #pragma unroll 4
    for (int kk = 0; kk < 256; kk += 8){
        FragA a0, a1; FragB b;
        wmma::load_matrix_sync(a0, Ap + kk, lda);
        wmma::load_matrix_sync(a1, Ap + (size_t)16*lda + kk, lda);
        wmma::load_matrix_sync(b, Bp + (size_t)kk*ldb, ldb);
        cvt_tf32_a(a0); cvt_tf32_a(a1); cvt_tf32_b(b);
        wmma::mma_sync(c0, a0, b, c0);
        wmma::mma_sync(c1, a1, b, c1);
    }
    wmma::store_matrix_sync(Cs + (wr*32)*72 + wc*16, c0, 72, wmma::mem_row_major);
    wmma::store_matrix_sync(Cs + (wr*32 + 16)*72 + wc*16, c1, 72, wmma::mem_row_major);
}

// z/r gates: gzr = Ah @ Wh[:, :512] + gx[:, :512]; z=sig -> g_z, r=sig, u=r*h -> g_u
__global__ void __launch_bounds__(256,2) gemm_zr(const float* __restrict__ Wh, int t){
    __shared__ __align__(16) float Cs[64*72];
    int j0 = blockIdx.x << 6;      // 0..511
    int r0 = blockIdx.y << 6;
    mma_tile64(g_Ah + (size_t)r0*HH, HH, Wh + j0, G3, Cs);
    __syncthreads();
    int tid = threadIdx.x;
    for (int e = tid; e < 64*64; e += 256){
        int lr = e >> 6, lc = e & 63;
        int r = r0 + lr;
        int j = j0 + lc;
        int b = r >> 8, n = r & 255;
        float val = Cs[lr*72 + lc] + g_gx[(((size_t)(b*TT + t))*NN + n)*G3 + j];
        if (j < HH){
            g_z[(size_t)r*HH + j] = sigmoidf_(val);
        } else {
            int j2 = j - HH;
            float rr = sigmoidf_(val);
            g_u[(size_t)r*HH + j2] = rr * g_h[(size_t)r*HH + j2];
        }
    }
}

// c gate + state update: c = tanh(Au @ Wh[:,512:] + gx[:,512:]); h = z*h + (1-z)*c
__global__ void __launch_bounds__(256,2) gemm_c(const float* __restrict__ Wh, int t){
    __shared__ __align__(16) float Cs[64*72];
    int j0 = blockIdx.x << 6;      // 0..255
    int r0 = blockIdx.y << 6;
    mma_tile64(g_Au + (size_t)r0*HH, HH, Wh + 512 + j0, G3, Cs);
    __syncthreads();
    int tid = threadIdx.x;
    for (int e = tid; e < 64*64; e += 256){
        int lr = e >> 6, lc = e & 63;
        int r = r0 + lr;
        int j = j0 + lc;
        int b = r >> 8, n = r & 255;
        float val = Cs[lr*72 + lc] + g_gx[(((size_t)(b*TT + t))*NN + n)*G3 + 512 + j];
        float c = tanhf(val);
        size_t idx = (size_t)r*HH + j;
        float zv = g_z[idx];
        float hn = zv * g_h[idx] + (1.0f - zv) * c;
        g_h[idx] = hn;
        g_hseq[(((size_t)(b*TT + t))*NN + n)*HH + j] = hn;
    }
}

// layer-1 gx: g_gx = g_Axseq @ Wx1 + b1   ([131072,256] x [256,768])
__global__ void __launch_bounds__(256,2) gemm_gx1(const float* __restrict__ Wx1,
                                                  const float* __restrict__ b1){
    __shared__ __align__(16) float Cs[64*72];
    int j0 = blockIdx.x << 6;      // 0..767
    int r0 = blockIdx.y << 6;
    mma_tile64(g_Axseq + (size_t)r0*HH, HH, Wx1 + j0, G3, Cs);
    __syncthreads();
    int tid = threadIdx.x;
    for (int e = tid; e < 64*64; e += 256){
        int lr = e >> 6, lc = e & 63;
        int r = r0 + lr;
        int j = j0 + lc;
        g_gx[(size_t)r*G3 + j] = Cs[lr*72 + lc] + b1[j];
    }
}

// ---------------- output head (R1-proven) ----------------
__global__ void out_head(const float* __restrict__ Wout, const float* __restrict__ bout,
                         float* __restrict__ out){
    __shared__ float sh[32*257];
    __shared__ float Ws[HH*DO];
    __shared__ float bs[DO];
    int r0 = blockIdx.x * 32;
    int tid = threadIdx.x;
    for (int i = tid; i < HH*DO; i += 256) Ws[i] = Wout[i];
    if (tid < DO) bs[tid] = bout[tid];
    const float4* H4 = (const float4*)g_hseq;
    for (int i = tid; i < 32*64; i += 256){
        int rr = i >> 6, c4 = i & 63;
        float4 v = H4[((size_t)(r0 + rr))*64 + c4];
        float* dst = &sh[rr*257 + c4*4];
        dst[0]=v.x; dst[1]=v.y; dst[2]=v.z; dst[3]=v.w;
    }
    __syncthreads();
    for (int oi = tid; oi < 32*DO; oi += 256){
        int rr = oi / DO, c = oi % DO;
        float a0 = bs[c], a1 = 0.0f;
        const float* sr = &sh[rr*257];
        for (int k = 0; k < HH; k += 2){
            a0 += sr[k]   * Ws[k*DO + c];
            a1 += sr[k+1] * Ws[(k+1)*DO + c];
        }
        out[(size_t)(r0 + rr)*DO + c] = a0 + a1;
    }
}

// ---------------- launch (R11 orchestration; GEMMs -> wmma tf32) ----------------
extern "C" void kernel_launch(void* const* d_in, const int* in_sizes, int n_in,
                              void* d_out, int out_size) {
    const float* x2d  = (const float*)d_in[0];
    const float* mask = (const float*)d_in[1];
    const float* adj  = (const float*)d_in[2];
    const float* Wx0  = (const float*)d_in[3];
    const float* Wh0  = (const float*)d_in[4];
    const float* b0   = (const float*)d_in[5];
    const float* Wx1  = (const float*)d_in[6];
    const float* Wh1  = (const float*)d_in[7];
    const float* b1   = (const float*)d_in[8];
    const float* Wout = (const float*)d_in[9];
    const float* bout = (const float*)d_in[10];
    float* out = (float*)d_out;

    build_csr<<<1, 256>>>(adj);
    prep_gx0<<<BB*TT, 256>>>(x2d, mask, Wx0, b0);

    // ---- layer 0 recurrence ----
    zero_h<<<2048, 256>>>();
    for (int t = 0; t < TT; t++){
        spconv_step<<<BB*NN, 64>>>(0);
        gemm_zr<<<dim3(8, (BB*NN)/64), 256>>>(Wh0, t);
        spconv_step<<<BB*NN, 64>>>(1);
        gemm_c<<<dim3(4, (BB*NN)/64), 256>>>(Wh0, t);
    }

    // ---- layer 1 gx precompute (parallel over all t) ----
    spconv_seq<<<dim3(8, BB*TT), 256>>>();
    gemm_gx1<<<dim3(12, (BB*TT*NN)/64), 256>>>(Wx1, b1);

    // ---- layer 1 recurrence ----
    zero_h<<<2048, 256>>>();
    for (int t = 0; t < TT; t++){
        spconv_step<<<BB*NN, 64>>>(0);
        gemm_zr<<<dim3(8, (BB*NN)/64), 256>>>(Wh1, t);
        spconv_step<<<BB*NN, 64>>>(1);
        gemm_c<<<dim3(4, (BB*NN)/64), 256>>>(Wh1, t);
    }

    // ---- output head ----
    out_head<<<(BB*TT*NN)/32, 256>>>(Wout, bout, out);
}

// round 13
// speedup vs baseline: 1.3212x; 1.3212x over previous
#include <cuda_runtime.h>
#include <math.h>
#include <mma.h>

using namespace nvcuda;

#define BB 8
#define TT 64
#define NN 256
#define HH 256
#define DI 6
#define DO 9
#define G3 (3*HH)   // 768

// ---------------- scratch (device globals; no runtime allocation) ----------------
__device__ __align__(16) float g_gx[(size_t)BB*TT*NN*G3];
__device__ __align__(16) float g_hseq[(size_t)BB*TT*NN*HH];
__device__ __align__(16) float g_Axseq[(size_t)BB*TT*NN*HH];
__device__ __align__(16) float g_h [BB*NN*HH];
__device__ __align__(16) float g_Ah[BB*NN*HH];
__device__ __align__(16) float g_z [BB*NN*HH];
__device__ __align__(16) float g_u [BB*NN*HH];
__device__ __align__(16) float g_Au[BB*NN*HH];
__device__ int   g_cnt[NN];
__device__ int   g_col[NN*NN];
__device__ float g_val[NN*NN];

__device__ __forceinline__ float sigmoidf_(float x){ return 1.0f / (1.0f + expf(-x)); }

typedef wmma::fragment<wmma::matrix_a, 16, 16, 8, wmma::precision::tf32, wmma::row_major> FragA;
typedef wmma::fragment<wmma::matrix_b, 16, 16, 8, wmma::precision::tf32, wmma::row_major> FragB;
typedef wmma::fragment<wmma::accumulator, 16, 16, 8, float> FragC;

__device__ __forceinline__ void cvt_tf32_a(FragA& f){
    #pragma unroll
    for (int i = 0; i < f.num_elements; i++) f.x[i] = wmma::__float_to_tf32(f.x[i]);
}
__device__ __forceinline__ void cvt_tf32_b(FragB& f){
    #pragma unroll
    for (int i = 0; i < f.num_elements; i++) f.x[i] = wmma::__float_to_tf32(f.x[i]);
}

// ---------------- CSR build from dense adjacency (zeros are exact) ----------------
__global__ void build_csr(const float* __restrict__ adj){
    int n = threadIdx.x;
    int c = 0;
    for (int m = 0; m < NN; m++){
        float v = adj[n*NN + m];
        if (v != 0.0f){ g_col[n*NN + c] = m; g_val[n*NN + c] = v; c++; }
    }
    g_cnt[n] = c;
}

__global__ void zero_h(){
    int i = blockIdx.x * 256 + threadIdx.x;
    g_h[i] = 0.0f;
}

// ---------------- layer-0 gx: per (b,t), gx = (A (x) (x*mask)) @ Wx0 + b0 ----------------
__global__ void prep_gx0(const float* __restrict__ x2d, const float* __restrict__ mask,
                         const float* __restrict__ Wx0, const float* __restrict__ b0){
    __shared__ float xm[NN*DI];
    __shared__ float ax[NN*DI];
    __shared__ float Ws[DI*G3];
    int bt = blockIdx.x;
    int tid = threadIdx.x;

    for (int i = tid; i < NN*DI; i += 256){
        int n = i / DI;
        xm[i] = x2d[(size_t)bt*NN*DI + i] * mask[(size_t)bt*NN + n];
    }
    for (int i = tid; i < DI*G3; i += 256) Ws[i] = Wx0[i];
    __syncthreads();

    {   // sparse conv: one node per thread
        int n = tid;
        float a0=0,a1=0,a2=0,a3=0,a4=0,a5=0;
        int cn = g_cnt[n];
        for (int e = 0; e < cn; e++){
            int m = g_col[n*NN + e];
            float w = g_val[n*NN + e];
            const float* xr = xm + m*DI;
            a0 += w*xr[0]; a1 += w*xr[1]; a2 += w*xr[2];
            a3 += w*xr[3]; a4 += w*xr[4]; a5 += w*xr[5];
        }
        float* ar = ax + n*DI;
        ar[0]=a0; ar[1]=a1; ar[2]=a2; ar[3]=a3; ar[4]=a4; ar[5]=a5;
    }
    __syncthreads();

    for (int jj = 0; jj < 3; jj++){
        int j = tid + (jj << 8);
        float w0=Ws[j], w1=Ws[G3+j], w2=Ws[2*G3+j], w3=Ws[3*G3+j], w4=Ws[4*G3+j], w5=Ws[5*G3+j];
        float bj = b0[j];
        float* gout = g_gx + (size_t)bt*NN*G3 + j;
        for (int n = 0; n < NN; n++){
            const float* axr = ax + n*DI;
            float s = bj + axr[0]*w0 + axr[1]*w1 + axr[2]*w2
                         + axr[3]*w3 + axr[4]*w4 + axr[5]*w5;
            gout[(size_t)n*G3] = s;
        }
    }
}

// ---------------- per-step sparse conv, float4-vectorized (R11-proven) ----------------
__global__ void __launch_bounds__(64,16) spconv_step(int which){
    const float* __restrict__ X = which ? g_u  : g_h;
    float* __restrict__       C = which ? g_Au : g_Ah;
    int n = blockIdx.x & 255;
    int q = blockIdx.x >> 8;
    int k4 = threadIdx.x;
    int cn = g_cnt[n];
    const int*   cp = g_col + n*NN;
    const float* vp = g_val + n*NN;
    const float4* Xb = (const float4*)(X + (size_t)q*NN*HH) + k4;
    float4 a0 = make_float4(0,0,0,0), a1 = a0, a2 = a0, a3 = a0;
    int e = 0;
    for (; e + 4 <= cn; e += 4){
        float w0 = vp[e],   w1 = vp[e+1], w2 = vp[e+2], w3 = vp[e+3];
        float4 x0 = Xb[(size_t)cp[e]   << 6];
        float4 x1 = Xb[(size_t)cp[e+1] << 6];
        float4 x2 = Xb[(size_t)cp[e+2] << 6];
        float4 x3 = Xb[(size_t)cp[e+3] << 6];
        a0.x += w0*x0.x; a0.y += w0*x0.y; a0.z += w0*x0.z; a0.w += w0*x0.w;
        a1.x += w1*x1.x; a1.y += w1*x1.y; a1.z += w1*x1.z; a1.w += w1*x1.w;
        a2.x += w2*x2.x; a2.y += w2*x2.y; a2.z += w2*x2.z; a2.w += w2*x2.w;
        a3.x += w3*x3.x; a3.y += w3*x3.y; a3.z += w3*x3.z; a3.w += w3*x3.w;
    }
    for (; e < cn; e++){
        float w = vp[e];
        float4 x = Xb[(size_t)cp[e] << 6];
        a0.x += w*x.x; a0.y += w*x.y; a0.z += w*x.z; a0.w += w*x.w;
    }
    float4 r;
    r.x = (a0.x + a1.x) + (a2.x + a3.x);
    r.y = (a0.y + a1.y) + (a2.y + a3.y);
    r.z = (a0.z + a1.z) + (a2.z + a3.z);
    r.w = (a0.w + a1.w) + (a2.w + a3.w);
    ((float4*)(C + (size_t)q*NN*HH + (n << 8)))[k4] = r;
}

// ---------------- sequence sparse conv (R1-proven): g_Axseq = A (x) g_hseq ----------------
__global__ void spconv_seq(){
    __shared__ float Xs[NN*32];
    int kh = blockIdx.x;       // 0..7
    int q  = blockIdx.y;       // 0..511
    int tid = threadIdx.x;
    const float4* X4 = (const float4*)g_hseq;
    float4* Xs4 = (float4*)Xs;
    for (int i = tid; i < NN*8; i += 256){
        int m = i >> 3, c4 = i & 7;
        Xs4[i] = X4[((size_t)q*NN + m)*64 + kh*8 + c4];
    }
    __syncthreads();
    int k  = tid & 31;
    int ng = tid >> 5;         // 0..7
    for (int nb = 0; nb < NN; nb += 8){
        int n = nb + ng;
        int cn = g_cnt[n];
        const int*   cp = g_col + n*NN;
        const float* vp = g_val + n*NN;
        float a0 = 0.0f, a1 = 0.0f;
        int e = 0;
        for (; e + 2 <= cn; e += 2){
            a0 += vp[e]   * Xs[(cp[e]   << 5) + k];
            a1 += vp[e+1] * Xs[(cp[e+1] << 5) + k];
        }
        if (e < cn) a0 += vp[e] * Xs[(cp[e] << 5) + k];
        g_Axseq[((size_t)q*NN + n)*HH + (kh << 5) + k] = a0 + a1;
    }
}

// ---------------- wmma tf32 64x64 tile, SMEM-STAGED, reg-prefetched ----------------
// SB layout: As = SB[0 .. 64*36), Bs = SB[2304 .. 2304+32*68); Cs overlays SB[0 .. 64*72).
// A chunk: 64 rows x 32 k; B chunk: 32 k x 64 cols. 512 float4 each; 2/thread.
#define SBSZ 4608
__device__ __forceinline__ void mma_tile64s(const float* __restrict__ Abase, int lda,
                                            const float* __restrict__ Bbase, int ldb,
                                            float* SB){
    float* As = SB;           // stride 36
    float* Bs = SB + 2304;    // stride 68
    int tid = threadIdx.x;
    int w = tid >> 5;
    int wr = w >> 2, wc = w & 3;

    // A f4 indices: i, i+256 ; row = i>>3, c4 = i&7
    int ia0 = tid, ia1 = tid + 256;
    int ar0 = ia0 >> 3, ac0 = (ia0 & 7) << 2;
    int ar1 = ia1 >> 3, ac1 = (ia1 & 7) << 2;
    // B f4 indices: krow = i>>4, c4 = i&15
    int br0 = tid >> 4, bc0 = (tid & 15) << 2;
    int br1 = (tid + 256) >> 4, bc1 = ((tid + 256) & 15) << 2;

    FragC c0, c1;
    wmma::fill_fragment(c0, 0.0f);
    wmma::fill_fragment(c1, 0.0f);

    float4 pa0 = *(const float4*)(Abase + (size_t)ar0*lda + ac0);
    float4 pa1 = *(const float4*)(Abase + (size_t)ar1*lda + ac1);
    float4 pb0 = *(const float4*)(Bbase + (size_t)br0*ldb + bc0);
    float4 pb1 = *(const float4*)(Bbase + (size_t)br1*ldb + bc1);

    for (int kb = 0; kb < 256; kb += 32){
        *(float4*)(As + ar0*36 + ac0) = pa0;
        *(float4*)(As + ar1*36 + ac1) = pa1;
        *(float4*)(Bs + br0*68 + bc0) = pb0;
        *(float4*)(Bs + br1*68 + bc1) = pb1;
        __syncthreads();
        if (kb + 32 < 256){
            pa0 = *(const float4*)(Abase + (size_t)ar0*lda + kb + 32 + ac0);
            pa1 = *(const float4*)(Abase + (size_t)ar1*lda + kb + 32 + ac1);
            pb0 = *(const float4*)(Bbase + (size_t)(kb + 32 + br0)*ldb + bc0);
            pb1 = *(const float4*)(Bbase + (size_t)(kb + 32 + br1)*ldb + bc1);
        }
        const float* Ap = As + (wr*32)*36;
        const float* Bp = Bs + wc*16;
        #pragma unroll
        for (int ks = 0; ks < 32; ks += 8){
            FragA a0, a1; FragB b;
            wmma::load_matrix_sync(a0, Ap + ks, 36);
            wmma::load_matrix_sync(a1, Ap + 16*36 + ks, 36);
            wmma::load_matrix_sync(b, Bp + ks*68, 68);
            cvt_tf32_a(a0); cvt_tf32_a(a1); cvt_tf32_b(b);
            wmma::mma_sync(c0, a0, b, c0);
            wmma::mma_sync(c1, a1, b, c1);
        }
        __syncthreads();
    }
    // Cs overlays As/Bs — all warps are past their last reads (sync above).
    float* Cs = SB;
    wmma::store_matrix_sync(Cs + (wr*32)*72 + wc*16, c0, 72, wmma::mem_row_major);
    wmma::store_matrix_sync(Cs + (wr*32 + 16)*72 + wc*16, c1, 72, wmma::mem_row_major);
}

// z/r gates: gzr = Ah @ Wh[:, :512] + gx[:, :512]; z=sig -> g_z, r=sig, u=r*h -> g_u
__global__ void __launch_bounds__(256,2) gemm_zr(const float* __restrict__ Wh, int t){
    __shared__ __align__(16) float SB[SBSZ];
    int j0 = blockIdx.x << 6;      // 0..511
    int r0 = blockIdx.y << 6;
    mma_tile64s(g_Ah + (size_t)r0*HH, HH, Wh + j0, G3, SB);
    __syncthreads();
    int tid = threadIdx.x;
    for (int e = tid; e < 64*64; e += 256){
        int lr = e >> 6, lc = e & 63;
        int r = r0 + lr;
        int j = j0 + lc;
        int b = r >> 8, n = r & 255;
        float val = SB[lr*72 + lc] + g_gx[(((size_t)(b*TT + t))*NN + n)*G3 + j];
        if (j < HH){
            g_z[(size_t)r*HH + j] = sigmoidf_(val);
        } else {
            int j2 = j - HH;
            float rr = sigmoidf_(val);
            g_u[(size_t)r*HH + j2] = rr * g_h[(size_t)r*HH + j2];
        }
    }
}

// c gate + state update: c = tanh(Au @ Wh[:,512:] + gx[:,512:]); h = z*h + (1-z)*c
__global__ void __launch_bounds__(256,2) gemm_c(const float* __restrict__ Wh, int t){
    __shared__ __align__(16) float SB[SBSZ];
    int j0 = blockIdx.x << 6;      // 0..255
    int r0 = blockIdx.y << 6;
    mma_tile64s(g_Au + (size_t)r0*HH, HH, Wh + 512 + j0, G3, SB);
    __syncthreads();
    int tid = threadIdx.x;
    for (int e = tid; e < 64*64; e += 256){
        int lr = e >> 6, lc = e & 63;
        int r = r0 + lr;
        int j = j0 + lc;
        int b = r >> 8, n = r & 255;
        float val = SB[lr*72 + lc] + g_gx[(((size_t)(b*TT + t))*NN + n)*G3 + 512 + j];
        float c = tanhf(val);
        size_t idx = (size_t)r*HH + j;
        float zv = g_z[idx];
        float hn = zv * g_h[idx] + (1.0f - zv) * c;
        g_h[idx] = hn;
        g_hseq[(((size_t)(b*TT + t))*NN + n)*HH + j] = hn;
    }
}

// layer-1 gx: g_gx = g_Axseq @ Wx1 + b1   ([131072,256] x [256,768])
__global__ void __launch_bounds__(256,2) gemm_gx1(const float* __restrict__ Wx1,
                                                  const float* __restrict__ b1){
    __shared__ __align__(16) float SB[SBSZ];
    int j0 = blockIdx.x << 6;      // 0..767
    int r0 = blockIdx.y << 6;
    mma_tile64s(g_Axseq + (size_t)r0*HH, HH, Wx1 + j0, G3, SB);
    __syncthreads();
    int tid = threadIdx.x;
    for (int e = tid; e < 64*64; e += 256){
        int lr = e >> 6, lc = e & 63;
        int r = r0 + lr;
        int j = j0 + lc;
        g_gx[(size_t)r*G3 + j] = SB[lr*72 + lc] + b1[j];
    }
}

// ---------------- output head (R1-proven) ----------------
__global__ void out_head(const float* __restrict__ Wout, const float* __restrict__ bout,
                         float* __restrict__ out){
    __shared__ float sh[32*257];
    __shared__ float Ws[HH*DO];
    __shared__ float bs[DO];
    int r0 = blockIdx.x * 32;
    int tid = threadIdx.x;
    for (int i = tid; i < HH*DO; i += 256) Ws[i] = Wout[i];
    if (tid < DO) bs[tid] = bout[tid];
    const float4* H4 = (const float4*)g_hseq;
    for (int i = tid; i < 32*64; i += 256){
        int rr = i >> 6, c4 = i & 63;
        float4 v = H4[((size_t)(r0 + rr))*64 + c4];
        float* dst = &sh[rr*257 + c4*4];
        dst[0]=v.x; dst[1]=v.y; dst[2]=v.z; dst[3]=v.w;
    }
    __syncthreads();
    for (int oi = tid; oi < 32*DO; oi += 256){
        int rr = oi / DO, c = oi % DO;
        float a0 = bs[c], a1 = 0.0f;
        const float* sr = &sh[rr*257];
        for (int k = 0; k < HH; k += 2){
            a0 += sr[k]   * Ws[k*DO + c];
            a1 += sr[k+1] * Ws[(k+1)*DO + c];
        }
        out[(size_t)(r0 + rr)*DO + c] = a0 + a1;
    }
}

// ---------------- launch (R11 orchestration; GEMMs -> staged wmma tf32) ----------------
extern "C" void kernel_launch(void* const* d_in, const int* in_sizes, int n_in,
                              void* d_out, int out_size) {
    const float* x2d  = (const float*)d_in[0];
    const float* mask = (const float*)d_in[1];
    const float* adj  = (const float*)d_in[2];
    const float* Wx0  = (const float*)d_in[3];
    const float* Wh0  = (const float*)d_in[4];
    const float* b0   = (const float*)d_in[5];
    const float* Wx1  = (const float*)d_in[6];
    const float* Wh1  = (const float*)d_in[7];
    const float* b1   = (const float*)d_in[8];
    const float* Wout = (const float*)d_in[9];
    const float* bout = (const float*)d_in[10];
    float* out = (float*)d_out;

    build_csr<<<1, 256>>>(adj);
    prep_gx0<<<BB*TT, 256>>>(x2d, mask, Wx0, b0);

    // ---- layer 0 recurrence ----
    zero_h<<<2048, 256>>>();
    for (int t = 0; t < TT; t++){
        spconv_step<<<BB*NN, 64>>>(0);
        gemm_zr<<<dim3(8, (BB*NN)/64), 256>>>(Wh0, t);
        spconv_step<<<BB*NN, 64>>>(1);
        gemm_c<<<dim3(4, (BB*NN)/64), 256>>>(Wh0, t);
    }

    // ---- layer 1 gx precompute (parallel over all t) ----
    spconv_seq<<<dim3(8, BB*TT), 256>>>();
    gemm_gx1<<<dim3(12, (BB*TT*NN)/64), 256>>>(Wx1, b1);

    // ---- layer 1 recurrence ----
    zero_h<<<2048, 256>>>();
    for (int t = 0; t < TT; t++){
        spconv_step<<<BB*NN, 64>>>(0);
        gemm_zr<<<dim3(8, (BB*NN)/64), 256>>>(Wh1, t);
        spconv_step<<<BB*NN, 64>>>(1);
        gemm_c<<<dim3(4, (BB*NN)/64), 256>>>(Wh1, t);
    }

    // ---- output head ----
    out_head<<<(BB*TT*NN)/32, 256>>>(Wout, bout, out);
}

// round 14
// speedup vs baseline: 1.3569x; 1.0270x over previous
#include <cuda_runtime.h>
#include <math.h>
#include <mma.h>

using namespace nvcuda;

#define BB 8
#define TT 64
#define NN 256
#define HH 256
#define DI 6
#define DO 9
#define G3 (3*HH)   // 768

// ---------------- scratch (device globals; no runtime allocation) ----------------
__device__ __align__(16) float g_gx[(size_t)BB*TT*NN*G3];
__device__ __align__(16) float g_hseq[(size_t)BB*TT*NN*HH];
__device__ __align__(16) float g_Axseq[(size_t)BB*TT*NN*HH];
__device__ __align__(16) float g_h [BB*NN*HH];
__device__ __align__(16) float g_Ah[BB*NN*HH];
__device__ __align__(16) float g_z [BB*NN*HH];
__device__ __align__(16) float g_u [BB*NN*HH];
__device__ __align__(16) float g_Au[BB*NN*HH];
__device__ int   g_cnt[NN];
__device__ int   g_col[NN*NN];
__device__ float g_val[NN*NN];

__device__ __forceinline__ float sigmoidf_(float x){ return 1.0f / (1.0f + expf(-x)); }

typedef wmma::fragment<wmma::matrix_a, 16, 16, 8, wmma::precision::tf32, wmma::row_major> FragA;
typedef wmma::fragment<wmma::matrix_b, 16, 16, 8, wmma::precision::tf32, wmma::row_major> FragB;
typedef wmma::fragment<wmma::accumulator, 16, 16, 8, float> FragC;

__device__ __forceinline__ void cvt_tf32_a(FragA& f){
    #pragma unroll
    for (int i = 0; i < f.num_elements; i++) f.x[i] = wmma::__float_to_tf32(f.x[i]);
}
__device__ __forceinline__ void cvt_tf32_b(FragB& f){
    #pragma unroll
    for (int i = 0; i < f.num_elements; i++) f.x[i] = wmma::__float_to_tf32(f.x[i]);
}

// ---------------- CSR build from dense adjacency (zeros are exact) ----------------
__global__ void build_csr(const float* __restrict__ adj){
    int n = threadIdx.x;
    int c = 0;
    for (int m = 0; m < NN; m++){
        float v = adj[n*NN + m];
        if (v != 0.0f){ g_col[n*NN + c] = m; g_val[n*NN + c] = v; c++; }
    }
    g_cnt[n] = c;
}

__global__ void zero_h(){
    int i = blockIdx.x * 256 + threadIdx.x;
    g_h[i] = 0.0f;
}

// ---------------- layer-0 gx: per (b,t), gx = (A (x) (x*mask)) @ Wx0 + b0 ----------------
__global__ void prep_gx0(const float* __restrict__ x2d, const float* __restrict__ mask,
                         const float* __restrict__ Wx0, const float* __restrict__ b0){
    __shared__ float xm[NN*DI];
    __shared__ float ax[NN*DI];
    __shared__ float Ws[DI*G3];
    int bt = blockIdx.x;
    int tid = threadIdx.x;

    for (int i = tid; i < NN*DI; i += 256){
        int n = i / DI;
        xm[i] = x2d[(size_t)bt*NN*DI + i] * mask[(size_t)bt*NN + n];
    }
    for (int i = tid; i < DI*G3; i += 256) Ws[i] = Wx0[i];
    __syncthreads();

    {   // sparse conv: one node per thread
        int n = tid;
        float a0=0,a1=0,a2=0,a3=0,a4=0,a5=0;
        int cn = g_cnt[n];
        for (int e = 0; e < cn; e++){
            int m = g_col[n*NN + e];
            float w = g_val[n*NN + e];
            const float* xr = xm + m*DI;
            a0 += w*xr[0]; a1 += w*xr[1]; a2 += w*xr[2];
            a3 += w*xr[3]; a4 += w*xr[4]; a5 += w*xr[5];
        }
        float* ar = ax + n*DI;
        ar[0]=a0; ar[1]=a1; ar[2]=a2; ar[3]=a3; ar[4]=a4; ar[5]=a5;
    }
    __syncthreads();

    for (int jj = 0; jj < 3; jj++){
        int j = tid + (jj << 8);
        float w0=Ws[j], w1=Ws[G3+j], w2=Ws[2*G3+j], w3=Ws[3*G3+j], w4=Ws[4*G3+j], w5=Ws[5*G3+j];
        float bj = b0[j];
        float* gout = g_gx + (size_t)bt*NN*G3 + j;
        for (int n = 0; n < NN; n++){
            const float* axr = ax + n*DI;
            float s = bj + axr[0]*w0 + axr[1]*w1 + axr[2]*w2
                         + axr[3]*w3 + axr[4]*w4 + axr[5]*w5;
            gout[(size_t)n*G3] = s;
        }
    }
}

// ---------------- per-step sparse conv, float4-vectorized (R11-proven) + PDL ----------------
__global__ void __launch_bounds__(64,16) spconv_step(int which){
    const float* __restrict__ X = which ? g_u  : g_h;
    float* __restrict__       C = which ? g_Au : g_Ah;
    int n = blockIdx.x & 255;
    int q = blockIdx.x >> 8;
    int k4 = threadIdx.x;
    // CSR metadata is static during the recurrence — safe to read pre-sync.
    int cn = g_cnt[n];
    const int*   cp = g_col + n*NN;
    const float* vp = g_val + n*NN;
    const float4* Xb = (const float4*)(X + (size_t)q*NN*HH) + k4;
    cudaGridDependencySynchronize();
    float4 a0 = make_float4(0,0,0,0), a1 = a0, a2 = a0, a3 = a0;
    int e = 0;
    for (; e + 4 <= cn; e += 4){
        float w0 = vp[e],   w1 = vp[e+1], w2 = vp[e+2], w3 = vp[e+3];
        float4 x0 = Xb[(size_t)cp[e]   << 6];
        float4 x1 = Xb[(size_t)cp[e+1] << 6];
        float4 x2 = Xb[(size_t)cp[e+2] << 6];
        float4 x3 = Xb[(size_t)cp[e+3] << 6];
        a0.x += w0*x0.x; a0.y += w0*x0.y; a0.z += w0*x0.z; a0.w += w0*x0.w;
        a1.x += w1*x1.x; a1.y += w1*x1.y; a1.z += w1*x1.z; a1.w += w1*x1.w;
        a2.x += w2*x2.x; a2.y += w2*x2.y; a2.z += w2*x2.z; a2.w += w2*x2.w;
        a3.x += w3*x3.x; a3.y += w3*x3.y; a3.z += w3*x3.z; a3.w += w3*x3.w;
    }
    for (; e < cn; e++){
        float w = vp[e];
        float4 x = Xb[(size_t)cp[e] << 6];
        a0.x += w*x.x; a0.y += w*x.y; a0.z += w*x.z; a0.w += w*x.w;
    }
    float4 r;
    r.x = (a0.x + a1.x) + (a2.x + a3.x);
    r.y = (a0.y + a1.y) + (a2.y + a3.y);
    r.z = (a0.z + a1.z) + (a2.z + a3.z);
    r.w = (a0.w + a1.w) + (a2.w + a3.w);
    ((float4*)(C + (size_t)q*NN*HH + (n << 8)))[k4] = r;
    cudaTriggerProgrammaticLaunchCompletion();
}

// ---------------- sequence sparse conv (R1-proven): g_Axseq = A (x) g_hseq ----------------
__global__ void spconv_seq(){
    __shared__ float Xs[NN*32];
    int kh = blockIdx.x;       // 0..7
    int q  = blockIdx.y;       // 0..511
    int tid = threadIdx.x;
    const float4* X4 = (const float4*)g_hseq;
    float4* Xs4 = (float4*)Xs;
    for (int i = tid; i < NN*8; i += 256){
        int m = i >> 3, c4 = i & 7;
        Xs4[i] = X4[((size_t)q*NN + m)*64 + kh*8 + c4];
    }
    __syncthreads();
    int k  = tid & 31;
    int ng = tid >> 5;         // 0..7
    for (int nb = 0; nb < NN; nb += 8){
        int n = nb + ng;
        int cn = g_cnt[n];
        const int*   cp = g_col + n*NN;
        const float* vp = g_val + n*NN;
        float a0 = 0.0f, a1 = 0.0f;
        int e = 0;
        for (; e + 2 <= cn; e += 2){
            a0 += vp[e]   * Xs[(cp[e]   << 5) + k];
            a1 += vp[e+1] * Xs[(cp[e+1] << 5) + k];
        }
        if (e < cn) a0 += vp[e] * Xs[(cp[e] << 5) + k];
        g_Axseq[((size_t)q*NN + n)*HH + (kh << 5) + k] = a0 + a1;
    }
}

// ---------------- wmma tf32 64x64 tile, SMEM-STAGED, reg-prefetched (R13-proven) ----------------
#define SBSZ 4608
__device__ __forceinline__ void mma_tile64s(const float* __restrict__ Abase, int lda,
                                            const float* __restrict__ Bbase, int ldb,
                                            float* SB){
    float* As = SB;           // stride 36
    float* Bs = SB + 2304;    // stride 68
    int tid = threadIdx.x;
    int w = tid >> 5;
    int wr = w >> 2, wc = w & 3;

    int ia0 = tid, ia1 = tid + 256;
    int ar0 = ia0 >> 3, ac0 = (ia0 & 7) << 2;
    int ar1 = ia1 >> 3, ac1 = (ia1 & 7) << 2;
    int br0 = tid >> 4, bc0 = (tid & 15) << 2;
    int br1 = (tid + 256) >> 4, bc1 = ((tid + 256) & 15) << 2;

    FragC c0, c1;
    wmma::fill_fragment(c0, 0.0f);
    wmma::fill_fragment(c1, 0.0f);

    float4 pa0 = *(const float4*)(Abase + (size_t)ar0*lda + ac0);
    float4 pa1 = *(const float4*)(Abase + (size_t)ar1*lda + ac1);
    float4 pb0 = *(const float4*)(Bbase + (size_t)br0*ldb + bc0);
    float4 pb1 = *(const float4*)(Bbase + (size_t)br1*ldb + bc1);

    for (int kb = 0; kb < 256; kb += 32){
        *(float4*)(As + ar0*36 + ac0) = pa0;
        *(float4*)(As + ar1*36 + ac1) = pa1;
        *(float4*)(Bs + br0*68 + bc0) = pb0;
        *(float4*)(Bs + br1*68 + bc1) = pb1;
        __syncthreads();
        if (kb + 32 < 256){
            pa0 = *(const float4*)(Abase + (size_t)ar0*lda + kb + 32 + ac0);
            pa1 = *(const float4*)(Abase + (size_t)ar1*lda + kb + 32 + ac1);
            pb0 = *(const float4*)(Bbase + (size_t)(kb + 32 + br0)*ldb + bc0);
            pb1 = *(const float4*)(Bbase + (size_t)(kb + 32 + br1)*ldb + bc1);
        }
        const float* Ap = As + (wr*32)*36;
        const float* Bp = Bs + wc*16;
        #pragma unroll
        for (int ks = 0; ks < 32; ks += 8){
            FragA a0, a1; FragB b;
            wmma::load_matrix_sync(a0, Ap + ks, 36);
            wmma::load_matrix_sync(a1, Ap + 16*36 + ks, 36);
            wmma::load_matrix_sync(b, Bp + ks*68, 68);
            cvt_tf32_a(a0); cvt_tf32_a(a1); cvt_tf32_b(b);
            wmma::mma_sync(c0, a0, b, c0);
            wmma::mma_sync(c1, a1, b, c1);
        }
        __syncthreads();
    }
    float* Cs = SB;
    wmma::store_matrix_sync(Cs + (wr*32)*72 + wc*16, c0, 72, wmma::mem_row_major);
    wmma::store_matrix_sync(Cs + (wr*32 + 16)*72 + wc*16, c1, 72, wmma::mem_row_major);
}

// z/r gates: gzr = Ah @ Wh[:, :512] + gx[:, :512]; z=sig -> g_z, r=sig, u=r*h -> g_u
__global__ void __launch_bounds__(256,2) gemm_zr(const float* __restrict__ Wh, int t){
    __shared__ __align__(16) float SB[SBSZ];
    int j0 = blockIdx.x << 6;      // 0..511
    int r0 = blockIdx.y << 6;
    cudaGridDependencySynchronize();
    mma_tile64s(g_Ah + (size_t)r0*HH, HH, Wh + j0, G3, SB);
    __syncthreads();
    int tid = threadIdx.x;
    for (int e = tid; e < 64*64; e += 256){
        int lr = e >> 6, lc = e & 63;
        int r = r0 + lr;
        int j = j0 + lc;
        int b = r >> 8, n = r & 255;
        float val = SB[lr*72 + lc] + g_gx[(((size_t)(b*TT + t))*NN + n)*G3 + j];
        if (j < HH){
            g_z[(size_t)r*HH + j] = sigmoidf_(val);
        } else {
            int j2 = j - HH;
            float rr = sigmoidf_(val);
            g_u[(size_t)r*HH + j2] = rr * g_h[(size_t)r*HH + j2];
        }
    }
    cudaTriggerProgrammaticLaunchCompletion();
}

// c gate + state update: c = tanh(Au @ Wh[:,512:] + gx[:,512:]); h = z*h + (1-z)*c
__global__ void __launch_bounds__(256,2) gemm_c(const float* __restrict__ Wh, int t){
    __shared__ __align__(16) float SB[SBSZ];
    int j0 = blockIdx.x << 6;      // 0..255
    int r0 = blockIdx.y << 6;
    cudaGridDependencySynchronize();
    mma_tile64s(g_Au + (size_t)r0*HH, HH, Wh + 512 + j0, G3, SB);
    __syncthreads();
    int tid = threadIdx.x;
    for (int e = tid; e < 64*64; e += 256){
        int lr = e >> 6, lc = e & 63;
        int r = r0 + lr;
        int j = j0 + lc;
        int b = r >> 8, n = r & 255;
        float val = SB[lr*72 + lc] + g_gx[(((size_t)(b*TT + t))*NN + n)*G3 + 512 + j];
        float c = tanhf(val);
        size_t idx = (size_t)r*HH + j;
        float zv = g_z[idx];
        float hn = zv * g_h[idx] + (1.0f - zv) * c;
        g_h[idx] = hn;
        g_hseq[(((size_t)(b*TT + t))*NN + n)*HH + j] = hn;
    }
    cudaTriggerProgrammaticLaunchCompletion();
}

// layer-1 gx: g_gx = g_Axseq @ Wx1 + b1   ([131072,256] x [256,768])
__global__ void __launch_bounds__(256,2) gemm_gx1(const float* __restrict__ Wx1,
                                                  const float* __restrict__ b1){
    __shared__ __align__(16) float SB[SBSZ];
    int j0 = blockIdx.x << 6;      // 0..767
    int r0 = blockIdx.y << 6;
    mma_tile64s(g_Axseq + (size_t)r0*HH, HH, Wx1 + j0, G3, SB);
    __syncthreads();
    int tid = threadIdx.x;
    for (int e = tid; e < 64*64; e += 256){
        int lr = e >> 6, lc = e & 63;
        int r = r0 + lr;
        int j = j0 + lc;
        g_gx[(size_t)r*G3 + j] = SB[lr*72 + lc] + b1[j];
    }
}

// ---------------- output head (R1-proven) ----------------
__global__ void out_head(const float* __restrict__ Wout, const float* __restrict__ bout,
                         float* __restrict__ out){
    __shared__ float sh[32*257];
    __shared__ float Ws[HH*DO];
    __shared__ float bs[DO];
    int r0 = blockIdx.x * 32;
    int tid = threadIdx.x;
    for (int i = tid; i < HH*DO; i += 256) Ws[i] = Wout[i];
    if (tid < DO) bs[tid] = bout[tid];
    const float4* H4 = (const float4*)g_hseq;
    for (int i = tid; i < 32*64; i += 256){
        int rr = i >> 6, c4 = i & 63;
        float4 v = H4[((size_t)(r0 + rr))*64 + c4];
        float* dst = &sh[rr*257 + c4*4];
        dst[0]=v.x; dst[1]=v.y; dst[2]=v.z; dst[3]=v.w;
    }
    __syncthreads();
    for (int oi = tid; oi < 32*DO; oi += 256){
        int rr = oi / DO, c = oi % DO;
        float a0 = bs[c], a1 = 0.0f;
        const float* sr = &sh[rr*257];
        for (int k = 0; k < HH; k += 2){
            a0 += sr[k]   * Ws[k*DO + c];
            a1 += sr[k+1] * Ws[(k+1)*DO + c];
        }
        out[(size_t)(r0 + rr)*DO + c] = a0 + a1;
    }
}

// ---------------- PDL launch helpers ----------------
static inline void pdl_conv(int which){
    cudaLaunchConfig_t cfg = {};
    cudaLaunchAttribute at[1];
    at[0].id = cudaLaunchAttributeProgrammaticStreamSerialization;
    at[0].val.programmaticStreamSerializationAllowed = 1;
    cfg.gridDim = dim3(BB*NN);
    cfg.blockDim = dim3(64);
    cfg.attrs = at;
    cfg.numAttrs = 1;
    cfg.stream = 0;
    cudaLaunchKernelEx(&cfg, spconv_step, which);
}
static inline void pdl_gemm(void (*kern)(const float*, int), dim3 grid,
                            const float* W, int t){
    cudaLaunchConfig_t cfg = {};
    cudaLaunchAttribute at[1];
    at[0].id = cudaLaunchAttributeProgrammaticStreamSerialization;
    at[0].val.programmaticStreamSerializationAllowed = 1;
    cfg.gridDim = grid;
    cfg.blockDim = dim3(256);
    cfg.attrs = at;
    cfg.numAttrs = 1;
    cfg.stream = 0;
    cudaLaunchKernelEx(&cfg, kern, W, t);
}

// ---------------- launch (R13 orchestration + PDL on recurrence) ----------------
extern "C" void kernel_launch(void* const* d_in, const int* in_sizes, int n_in,
                              void* d_out, int out_size) {
    const float* x2d  = (const float*)d_in[0];
    const float* mask = (const float*)d_in[1];
    const float* adj  = (const float*)d_in[2];
    const float* Wx0  = (const float*)d_in[3];
    const float* Wh0  = (const float*)d_in[4];
    const float* b0   = (const float*)d_in[5];
    const float* Wx1  = (const float*)d_in[6];
    const float* Wh1  = (const float*)d_in[7];
    const float* b1   = (const float*)d_in[8];
    const float* Wout = (const float*)d_in[9];
    const float* bout = (const float*)d_in[10];
    float* out = (float*)d_out;

    build_csr<<<1, 256>>>(adj);
    prep_gx0<<<BB*TT, 256>>>(x2d, mask, Wx0, b0);

    // ---- layer 0 recurrence ----
    zero_h<<<2048, 256>>>();
    for (int t = 0; t < TT; t++){
        pdl_conv(0);
        pdl_gemm(gemm_zr, dim3(8, (BB*NN)/64), Wh0, t);
        pdl_conv(1);
        pdl_gemm(gemm_c, dim3(4, (BB*NN)/64), Wh0, t);
    }

    // ---- layer 1 gx precompute (parallel over all t) ----
    spconv_seq<<<dim3(8, BB*TT), 256>>>();
    gemm_gx1<<<dim3(12, (BB*TT*NN)/64), 256>>>(Wx1, b1);

    // ---- layer 1 recurrence ----
    zero_h<<<2048, 256>>>();
    for (int t = 0; t < TT; t++){
        pdl_conv(0);
        pdl_gemm(gemm_zr, dim3(8, (BB*NN)/64), Wh1, t);
        pdl_conv(1);
        pdl_gemm(gemm_c, dim3(4, (BB*NN)/64), Wh1, t);
    }

    // ---- output head ----
    out_head<<<(BB*TT*NN)/32, 256>>>(Wout, bout, out);
}

// round 16
// speedup vs baseline: 1.7161x; 1.2647x over previous
#include <cuda_runtime.h>
#include <math.h>
#include <mma.h>

using namespace nvcuda;

#define BB 8
#define TT 64
#define NN 256
#define HH 256
#define DI 6
#define DO 9
#define G3 (3*HH)   // 768
#define RS 512      // row stride of layer-concat state buffers

// ---------------- scratch (device globals) ----------------
__device__ __align__(16) float g_gx[(size_t)BB*TT*NN*G3];    // layer-0 gx only
__device__ __align__(16) float g_hseq[(size_t)BB*TT*NN*HH];  // layer-1 hidden sequence
__device__ __align__(16) float g_hh [BB*NN*RS];   // [q][n][ L0 h | L1 h ]
__device__ __align__(16) float g_Ahh[BB*NN*RS];   // [q][n][ A(x)h0 | A(x)h1 ]
__device__ __align__(16) float g_uu [BB*NN*RS];
__device__ __align__(16) float g_Auu[BB*NN*RS];
__device__ __align__(16) float g_zz [BB*NN*RS];
__device__ int   g_cnt[NN];
__device__ int   g_col[NN*NN];
__device__ float g_val[NN*NN];

__device__ __forceinline__ float sigmoidf_(float x){ return 1.0f / (1.0f + expf(-x)); }

typedef wmma::fragment<wmma::matrix_a, 16, 16, 8, wmma::precision::tf32, wmma::row_major> FragA;
typedef wmma::fragment<wmma::matrix_b, 16, 16, 8, wmma::precision::tf32, wmma::row_major> FragB;
typedef wmma::fragment<wmma::accumulator, 16, 16, 8, float> FragC;

__device__ __forceinline__ void cvt_tf32_a(FragA& f){
    #pragma unroll
    for (int i = 0; i < f.num_elements; i++) f.x[i] = wmma::__float_to_tf32(f.x[i]);
}
__device__ __forceinline__ void cvt_tf32_b(FragB& f){
    #pragma unroll
    for (int i = 0; i < f.num_elements; i++) f.x[i] = wmma::__float_to_tf32(f.x[i]);
}

// ---------------- CSR build ----------------
__global__ void build_csr(const float* __restrict__ adj){
    int n = threadIdx.x;
    int c = 0;
    for (int m = 0; m < NN; m++){
        float v = adj[n*NN + m];
        if (v != 0.0f){ g_col[n*NN + c] = m; g_val[n*NN + c] = v; c++; }
    }
    g_cnt[n] = c;
}

__global__ void zero_hh(){
    ((float4*)g_hh)[blockIdx.x*256 + threadIdx.x] = make_float4(0,0,0,0);
}

// ---------------- layer-0 gx: per (b,t), gx = (A (x) (x*mask)) @ Wx0 + b0 ----------------
__global__ void prep_gx0(const float* __restrict__ x2d, const float* __restrict__ mask,
                         const float* __restrict__ Wx0, const float* __restrict__ b0){
    __shared__ float xm[NN*DI];
    __shared__ float ax[NN*DI];
    __shared__ float Ws[DI*G3];
    int bt = blockIdx.x;
    int tid = threadIdx.x;

    for (int i = tid; i < NN*DI; i += 256){
        int n = i / DI;
        xm[i] = x2d[(size_t)bt*NN*DI + i] * mask[(size_t)bt*NN + n];
    }
    for (int i = tid; i < DI*G3; i += 256) Ws[i] = Wx0[i];
    __syncthreads();

    {
        int n = tid;
        float a0=0,a1=0,a2=0,a3=0,a4=0,a5=0;
        int cn = g_cnt[n];
        for (int e = 0; e < cn; e++){
            int m = g_col[n*NN + e];
            float w = g_val[n*NN + e];
            const float* xr = xm + m*DI;
            a0 += w*xr[0]; a1 += w*xr[1]; a2 += w*xr[2];
            a3 += w*xr[3]; a4 += w*xr[4]; a5 += w*xr[5];
        }
        float* ar = ax + n*DI;
        ar[0]=a0; ar[1]=a1; ar[2]=a2; ar[3]=a3; ar[4]=a4; ar[5]=a5;
    }
    __syncthreads();

    for (int jj = 0; jj < 3; jj++){
        int j = tid + (jj << 8);
        float w0=Ws[j], w1=Ws[G3+j], w2=Ws[2*G3+j], w3=Ws[3*G3+j], w4=Ws[4*G3+j], w5=Ws[5*G3+j];
        float bj = b0[j];
        float* gout = g_gx + (size_t)bt*NN*G3 + j;
        for (int n = 0; n < NN; n++){
            const float* axr = ax + n*DI;
            float s = bj + axr[0]*w0 + axr[1]*w1 + axr[2]*w2
                         + axr[3]*w3 + axr[4]*w4 + axr[5]*w5;
            gout[(size_t)n*G3] = s;
        }
    }
}

// ---------------- per-step sparse conv, both layers (R11 core) + PDL ----------------
// grid 4096: bid = L*2048 + q*256 + n; 64 threads (4 cols each).
__global__ void __launch_bounds__(64,16) conv_step(int which){
    int bid = blockIdx.x;
    int L = bid >> 11;
    int q = (bid >> 8) & 7;
    int n = bid & 255;
    int k4 = threadIdx.x;
    const float* __restrict__ X = which ? g_uu  : g_hh;
    float* __restrict__       C = which ? g_Auu : g_Ahh;
    int cn = g_cnt[n];
    const int*   cp = g_col + n*NN;
    const float* vp = g_val + n*NN;
    const float4* Xb = (const float4*)(X + ((size_t)(q<<8))*RS + L*256) + k4;
    cudaGridDependencySynchronize();
    float4 a0 = make_float4(0,0,0,0), a1 = a0, a2 = a0, a3 = a0;
    int e = 0;
    for (; e + 4 <= cn; e += 4){
        float w0 = vp[e],   w1 = vp[e+1], w2 = vp[e+2], w3 = vp[e+3];
        float4 x0 = Xb[(size_t)cp[e]   << 7];
        float4 x1 = Xb[(size_t)cp[e+1] << 7];
        float4 x2 = Xb[(size_t)cp[e+2] << 7];
        float4 x3 = Xb[(size_t)cp[e+3] << 7];
        a0.x += w0*x0.x; a0.y += w0*x0.y; a0.z += w0*x0.z; a0.w += w0*x0.w;
        a1.x += w1*x1.x; a1.y += w1*x1.y; a1.z += w1*x1.z; a1.w += w1*x1.w;
        a2.x += w2*x2.x; a2.y += w2*x2.y; a2.z += w2*x2.z; a2.w += w2*x2.w;
        a3.x += w3*x3.x; a3.y += w3*x3.y; a3.z += w3*x3.z; a3.w += w3*x3.w;
    }
    for (; e < cn; e++){
        float w = vp[e];
        float4 x = Xb[(size_t)cp[e] << 7];
        a0.x += w*x.x; a0.y += w*x.y; a0.z += w*x.z; a0.w += w*x.w;
    }
    float4 r;
    r.x = (a0.x + a1.x) + (a2.x + a3.x);
    r.y = (a0.y + a1.y) + (a2.y + a3.y);
    r.z = (a0.z + a1.z) + (a2.z + a3.z);
    r.w = (a0.w + a1.w) + (a2.w + a3.w);
    ((float4*)(C + ((size_t)(q<<8) + n)*RS + L*256))[k4] = r;
    cudaTriggerProgrammaticLaunchCompletion();
}

// ---------------- wmma tf32 64x64 tile core, runtime K, lambda loaders ----------------
#define SBSZ 4608
template<class AF, class BF>
__device__ __forceinline__ void mma_core(AF ald, BF bld, int KLEN, float* SB){
    float* As = SB;           // stride 36
    float* Bs = SB + 2304;    // stride 68
    int tid = threadIdx.x;
    int w = tid >> 5;
    int wr = w >> 2, wc = w & 3;

    int ar0 = tid >> 3,        ac0 = (tid & 7) << 2;
    int ar1 = (tid+256) >> 3,  ac1 = ((tid+256) & 7) << 2;
    int br0 = tid >> 4,        bc0 = (tid & 15) << 2;
    int br1 = (tid+256) >> 4,  bc1 = ((tid+256) & 15) << 2;

    FragC c0, c1;
    wmma::fill_fragment(c0, 0.0f);
    wmma::fill_fragment(c1, 0.0f);

    float4 pa0 = ald(ar0, ac0);
    float4 pa1 = ald(ar1, ac1);
    float4 pb0 = bld(br0, bc0);
    float4 pb1 = bld(br1, bc1);

    for (int kb = 0; kb < KLEN; kb += 32){
        *(float4*)(As + ar0*36 + ac0) = pa0;
        *(float4*)(As + ar1*36 + ac1) = pa1;
        *(float4*)(Bs + br0*68 + bc0) = pb0;
        *(float4*)(Bs + br1*68 + bc1) = pb1;
        __syncthreads();
        if (kb + 32 < KLEN){
            pa0 = ald(ar0, kb + 32 + ac0);
            pa1 = ald(ar1, kb + 32 + ac1);
            pb0 = bld(kb + 32 + br0, bc0);
            pb1 = bld(kb + 32 + br1, bc1);
        }
        const float* Ap = As + (wr*32)*36;
        const float* Bp = Bs + wc*16;
        #pragma unroll
        for (int ks = 0; ks < 32; ks += 8){
            FragA a0, a1; FragB b;
            wmma::load_matrix_sync(a0, Ap + ks, 36);
            wmma::load_matrix_sync(a1, Ap + 16*36 + ks, 36);
            wmma::load_matrix_sync(b, Bp + ks*68, 68);
            cvt_tf32_a(a0); cvt_tf32_a(a1); cvt_tf32_b(b);
            wmma::mma_sync(c0, a0, b, c0);
            wmma::mma_sync(c1, a1, b, c1);
        }
        __syncthreads();
    }
    float* Cs = SB;
    wmma::store_matrix_sync(Cs + (wr*32)*72 + wc*16, c0, 72, wmma::mem_row_major);
    wmma::store_matrix_sync(Cs + (wr*32 + 16)*72 + wc*16, c1, 72, wmma::mem_row_major);
}

// ---------------- fused gate GEMMs, both layers via blockIdx.z ----------------
// GATE=0 (zr): grid (8, 32, 2). L0: Ah0@Wh0[:, :512] + gx ; L1: [Ah0|Ah1]@[Wx1;Wh1][:, :512] + b1
// GATE=1 (c):  grid (4, 32, 2). L0: Au0@Wh0[:,512:] + gx ; L1: [Ah0|Au1]@[Wx1;Wh1][:,512:] + b1
template<int GATE>
__global__ void __launch_bounds__(256,2) gemm_gate(const float* __restrict__ Wh0,
                                                   const float* __restrict__ Wx1,
                                                   const float* __restrict__ Wh1,
                                                   const float* __restrict__ b1,
                                                   int t, int act0, int act1){
    __shared__ __align__(16) float SB[SBSZ];
    int L = blockIdx.z;
    if (L ? !act1 : !act0) return;
    int j0 = blockIdx.x << 6;
    int r0 = blockIdx.y << 6;
    int KL = L ? 512 : 256;
    int goff = GATE ? 512 : 0;

    cudaGridDependencySynchronize();

    auto ald = [&](int row, int col)->float4 {
        const float* base;
        if (GATE == 0){
            base = g_Ahh;                         // L0: cols 0:256; L1: cols 0:512
        } else {
            base = (L == 1 && col < 256) ? g_Ahh : g_Auu;  // L1 c: [Ah0 | Au1]; L0 c: Au0
        }
        return *(const float4*)(base + (size_t)(r0 + row)*RS + col);
    };
    auto bld = [&](int k, int c)->float4 {
        const float* p;
        if (L == 0) p = Wh0 + (size_t)k*G3 + goff + j0 + c;
        else p = (k < 256) ? (Wx1 + (size_t)k*G3 + goff + j0 + c)
                           : (Wh1 + (size_t)(k-256)*G3 + goff + j0 + c);
        return *(const float4*)p;
    };

    mma_core(ald, bld, KL, SB);
    __syncthreads();

    int tid = threadIdx.x;
    for (int e = tid; e < 64*64; e += 256){
        int lr = e >> 6, lc = e & 63;
        int r = r0 + lr;
        int j = j0 + lc;
        int q = r >> 8, n = r & 255;
        float add;
        if (L == 0) add = g_gx[(((size_t)(q*TT + t))*NN + n)*G3 + goff + j];
        else        add = b1[goff + j];
        float val = SB[lr*72 + lc] + add;
        size_t base = (size_t)r*RS + L*256;
        if (GATE == 0){
            float s = sigmoidf_(val);
            if (j < 256){
                g_zz[base + j] = s;
            } else {
                int j2 = j - 256;
                g_uu[base + j2] = s * g_hh[base + j2];
            }
        } else {
            float c = tanhf(val);
            size_t idx = base + j;
            float zv = g_zz[idx];
            float hn = zv * g_hh[idx] + (1.0f - zv) * c;
            g_hh[idx] = hn;
            if (L == 1)
                g_hseq[(((size_t)(q*TT + (t-1)))*NN + n)*HH + j] = hn;
        }
    }
    cudaTriggerProgrammaticLaunchCompletion();
}

// ---------------- output head (reads layer-1 hseq) ----------------
__global__ void out_head(const float* __restrict__ Wout, const float* __restrict__ bout,
                         float* __restrict__ out){
    __shared__ float sh[32*257];
    __shared__ float Ws[HH*DO];
    __shared__ float bs[DO];
    int r0 = blockIdx.x * 32;
    int tid = threadIdx.x;
    for (int i = tid; i < HH*DO; i += 256) Ws[i] = Wout[i];
    if (tid < DO) bs[tid] = bout[tid];
    const float4* H4 = (const float4*)g_hseq;
    for (int i = tid; i < 32*64; i += 256){
        int rr = i >> 6, c4 = i & 63;
        float4 v = H4[((size_t)(r0 + rr))*64 + c4];
        float* dst = &sh[rr*257 + c4*4];
        dst[0]=v.x; dst[1]=v.y; dst[2]=v.z; dst[3]=v.w;
    }
    __syncthreads();
    for (int oi = tid; oi < 32*DO; oi += 256){
        int rr = oi / DO, c = oi % DO;
        float a0 = bs[c], a1 = 0.0f;
        const float* sr = &sh[rr*257];
        for (int k = 0; k < HH; k += 2){
            a0 += sr[k]   * Ws[k*DO + c];
            a1 += sr[k+1] * Ws[(k+1)*DO + c];
        }
        out[(size_t)(r0 + rr)*DO + c] = a0 + a1;
    }
}

// ---------------- PDL launch helpers ----------------
static inline void pdl_conv(int which){
    cudaLaunchConfig_t cfg = {};
    cudaLaunchAttribute at[1];
    at[0].id = cudaLaunchAttributeProgrammaticStreamSerialization;
    at[0].val.programmaticStreamSerializationAllowed = 1;
    cfg.gridDim = dim3(2*BB*NN);
    cfg.blockDim = dim3(64);
    cfg.attrs = at;
    cfg.numAttrs = 1;
    cfg.stream = 0;
    cudaLaunchKernelEx(&cfg, conv_step, which);
}
template<int GATE>
static inline void pdl_gate(dim3 grid, const float* Wh0, const float* Wx1,
                            const float* Wh1, const float* b1, int t, int a0, int a1){
    cudaLaunchConfig_t cfg = {};
    cudaLaunchAttribute at[1];
    at[0].id = cudaLaunchAttributeProgrammaticStreamSerialization;
    at[0].val.programmaticStreamSerializationAllowed = 1;
    cfg.gridDim = grid;
    cfg.blockDim = dim3(256);
    cfg.attrs = at;
    cfg.numAttrs = 1;
    cfg.stream = 0;
    cudaLaunchKernelEx(&cfg, gemm_gate<GATE>, Wh0, Wx1, Wh1, b1, t, a0, a1);
}

// ---------------- launch: pipelined 2-layer recurrence, 65 super-steps ----------------
extern "C" void kernel_launch(void* const* d_in, const int* in_sizes, int n_in,
                              void* d_out, int out_size) {
    const float* x2d  = (const float*)d_in[0];
    const float* mask = (const float*)d_in[1];
    const float* adj  = (const float*)d_in[2];
    const float* Wx0  = (const float*)d_in[3];
    const float* Wh0  = (const float*)d_in[4];
    const float* b0   = (const float*)d_in[5];
    const float* Wx1  = (const float*)d_in[6];
    const float* Wh1  = (const float*)d_in[7];
    const float* b1   = (const float*)d_in[8];
    const float* Wout = (const float*)d_in[9];
    const float* bout = (const float*)d_in[10];
    float* out = (float*)d_out;

    build_csr<<<1, 256>>>(adj);
    prep_gx0<<<BB*TT, 256>>>(x2d, mask, Wx0, b0);
    zero_hh<<<1024, 256>>>();

    for (int t = 0; t <= TT; t++){
        int a0 = (t < TT) ? 1 : 0;
        int a1 = (t > 0) ? 1 : 0;
        pdl_conv(0);                                                    // Ah0|Ah1
        pdl_gate<0>(dim3(8, 32, 2), Wh0, Wx1, Wh1, b1, t, a0, a1);      // z,r,u both layers
        pdl_conv(1);                                                    // Au0|Au1
        pdl_gate<1>(dim3(4, 32, 2), Wh0, Wx1, Wh1, b1, t, a0, a1);      // c + h update
    }

    out_head<<<(BB*TT*NN)/32, 256>>>(Wout, bout, out);
}

// round 17
// speedup vs baseline: 1.7664x; 1.0294x over previous
#include <cuda_runtime.h>
#include <math.h>
#include <mma.h>

using namespace nvcuda;

#define BB 8
#define TT 64
#define NN 256
#define HH 256
#define DI 6
#define DO 9
#define G3 (3*HH)   // 768
#define RS 512      // row stride of layer-concat state buffers

// ---------------- scratch (device globals) ----------------
__device__ __align__(16) float g_gx[(size_t)BB*TT*NN*G3];    // layer-0 gx only
__device__ __align__(16) float g_hseq[(size_t)BB*TT*NN*HH];  // layer-1 hidden sequence
__device__ __align__(16) float g_hh [BB*NN*RS];   // [q][n][ h0 | h1 ]
__device__ __align__(16) float g_Ahh[BB*NN*RS];   // [q][n][ Ah0 | Ah1 ]
__device__ __align__(16) float g_uu [BB*NN*RS];   // [q][n][ u0 | u1 ]
__device__ __align__(16) float g_zz [BB*NN*RS];   // [q][n][ z0 | z1 ]
__device__ __align__(16) float g_Acc[BB*NN*768];  // [q][n][ Au0 | Ah0 | Au1 ]
__device__ __align__(16) float g_Wcat[512*G3];    // [ Wx1 ; Wh1 ]
__device__ int   g_cnt[NN];
__device__ int   g_col[NN*NN];
__device__ float g_val[NN*NN];

__device__ __forceinline__ float sigmoidf_(float x){ return 1.0f / (1.0f + expf(-x)); }

typedef wmma::fragment<wmma::matrix_a, 16, 16, 8, wmma::precision::tf32, wmma::row_major> FragA;
typedef wmma::fragment<wmma::matrix_b, 16, 16, 8, wmma::precision::tf32, wmma::row_major> FragB;
typedef wmma::fragment<wmma::accumulator, 16, 16, 8, float> FragC;

__device__ __forceinline__ void cvt_tf32_a(FragA& f){
    #pragma unroll
    for (int i = 0; i < f.num_elements; i++) f.x[i] = wmma::__float_to_tf32(f.x[i]);
}
__device__ __forceinline__ void cvt_tf32_b(FragB& f){
    #pragma unroll
    for (int i = 0; i < f.num_elements; i++) f.x[i] = wmma::__float_to_tf32(f.x[i]);
}

// ---------------- CSR build ----------------
__global__ void build_csr(const float* __restrict__ adj){
    int n = threadIdx.x;
    int c = 0;
    for (int m = 0; m < NN; m++){
        float v = adj[n*NN + m];
        if (v != 0.0f){ g_col[n*NN + c] = m; g_val[n*NN + c] = v; c++; }
    }
    g_cnt[n] = c;
}

// pack [Wx1; Wh1] into g_Wcat (same [k][G3] layout as Wh0)
__global__ void prep_wcat(const float* __restrict__ Wx1, const float* __restrict__ Wh1){
    int i = blockIdx.x * 256 + threadIdx.x;      // 0 .. 512*768-1
    g_Wcat[i] = (i < 256*G3) ? Wx1[i] : Wh1[i - 256*G3];
}

__global__ void zero_hh(){
    ((float4*)g_hh)[blockIdx.x*256 + threadIdx.x] = make_float4(0,0,0,0);
}

// ---------------- layer-0 gx: per (b,t), gx = (A (x) (x*mask)) @ Wx0 + b0 ----------------
__global__ void prep_gx0(const float* __restrict__ x2d, const float* __restrict__ mask,
                         const float* __restrict__ Wx0, const float* __restrict__ b0){
    __shared__ float xm[NN*DI];
    __shared__ float ax[NN*DI];
    __shared__ float Ws[DI*G3];
    int bt = blockIdx.x;
    int tid = threadIdx.x;

    for (int i = tid; i < NN*DI; i += 256){
        int n = i / DI;
        xm[i] = x2d[(size_t)bt*NN*DI + i] * mask[(size_t)bt*NN + n];
    }
    for (int i = tid; i < DI*G3; i += 256) Ws[i] = Wx0[i];
    __syncthreads();

    {
        int n = tid;
        float a0=0,a1=0,a2=0,a3=0,a4=0,a5=0;
        int cn = g_cnt[n];
        for (int e = 0; e < cn; e++){
            int m = g_col[n*NN + e];
            float w = g_val[n*NN + e];
            const float* xr = xm + m*DI;
            a0 += w*xr[0]; a1 += w*xr[1]; a2 += w*xr[2];
            a3 += w*xr[3]; a4 += w*xr[4]; a5 += w*xr[5];
        }
        float* ar = ax + n*DI;
        ar[0]=a0; ar[1]=a1; ar[2]=a2; ar[3]=a3; ar[4]=a4; ar[5]=a5;
    }
    __syncthreads();

    for (int jj = 0; jj < 3; jj++){
        int j = tid + (jj << 8);
        float w0=Ws[j], w1=Ws[G3+j], w2=Ws[2*G3+j], w3=Ws[3*G3+j], w4=Ws[4*G3+j], w5=Ws[5*G3+j];
        float bj = b0[j];
        float* gout = g_gx + (size_t)bt*NN*G3 + j;
        for (int n = 0; n < NN; n++){
            const float* axr = ax + n*DI;
            float s = bj + axr[0]*w0 + axr[1]*w1 + axr[2]*w2
                         + axr[3]*w3 + axr[4]*w4 + axr[5]*w5;
            gout[(size_t)n*G3] = s;
        }
    }
}

// ---------------- per-step sparse conv, both layers (R16 core) + PDL ----------------
// which=0: Ah from g_hh.  L0 -> g_Ahh[0:256] AND g_Acc[256:512];  L1 -> g_Ahh[256:512]
// which=1: Au from g_uu.  L0 -> g_Acc[0:256];                     L1 -> g_Acc[512:768]
__global__ void __launch_bounds__(64,16) conv_step(int which){
    int bid = blockIdx.x;
    int L = bid >> 11;
    int q = (bid >> 8) & 7;
    int n = bid & 255;
    int k4 = threadIdx.x;
    const float* __restrict__ X = which ? g_uu : g_hh;
    int cn = g_cnt[n];
    const int*   cp = g_col + n*NN;
    const float* vp = g_val + n*NN;
    const float4* Xb = (const float4*)(X + ((size_t)(q<<8))*RS + L*256) + k4;
    cudaGridDependencySynchronize();
    float4 a0 = make_float4(0,0,0,0), a1 = a0, a2 = a0, a3 = a0;
    int e = 0;
    for (; e + 4 <= cn; e += 4){
        float w0 = vp[e],   w1 = vp[e+1], w2 = vp[e+2], w3 = vp[e+3];
        float4 x0 = Xb[(size_t)cp[e]   << 7];
        float4 x1 = Xb[(size_t)cp[e+1] << 7];
        float4 x2 = Xb[(size_t)cp[e+2] << 7];
        float4 x3 = Xb[(size_t)cp[e+3] << 7];
        a0.x += w0*x0.x; a0.y += w0*x0.y; a0.z += w0*x0.z; a0.w += w0*x0.w;
        a1.x += w1*x1.x; a1.y += w1*x1.y; a1.z += w1*x1.z; a1.w += w1*x1.w;
        a2.x += w2*x2.x; a2.y += w2*x2.y; a2.z += w2*x2.z; a2.w += w2*x2.w;
        a3.x += w3*x3.x; a3.y += w3*x3.y; a3.z += w3*x3.z; a3.w += w3*x3.w;
    }
    for (; e < cn; e++){
        float w = vp[e];
        float4 x = Xb[(size_t)cp[e] << 7];
        a0.x += w*x.x; a0.y += w*x.y; a0.z += w*x.z; a0.w += w*x.w;
    }
    float4 r;
    r.x = (a0.x + a1.x) + (a2.x + a3.x);
    r.y = (a0.y + a1.y) + (a2.y + a3.y);
    r.z = (a0.z + a1.z) + (a2.z + a3.z);
    r.w = (a0.w + a1.w) + (a2.w + a3.w);

    size_t row = (size_t)(q<<8) + n;
    if (which == 0){
        if (L == 0){
            ((float4*)(g_Ahh + row*RS))[k4] = r;
            ((float4*)(g_Acc + row*768 + 256))[k4] = r;
        } else {
            ((float4*)(g_Ahh + row*RS + 256))[k4] = r;
        }
    } else {
        if (L == 0) ((float4*)(g_Acc + row*768))[k4] = r;
        else        ((float4*)(g_Acc + row*768 + 512))[k4] = r;
    }
    cudaTriggerProgrammaticLaunchCompletion();
}

// ---------------- wmma tf32 64x64 tile core, runtime K, branch-free loaders ----------------
#define SBSZ 4608
__device__ __forceinline__ void mma_core(const float* __restrict__ Abase, int Alds,
                                         const float* __restrict__ Bbase,
                                         int KLEN, float* SB){
    float* As = SB;           // stride 36
    float* Bs = SB + 2304;    // stride 68
    int tid = threadIdx.x;
    int w = tid >> 5;
    int wr = w >> 2, wc = w & 3;

    int ar0 = tid >> 3,        ac0 = (tid & 7) << 2;
    int ar1 = (tid+256) >> 3,  ac1 = ((tid+256) & 7) << 2;
    int br0 = tid >> 4,        bc0 = (tid & 15) << 2;
    int br1 = (tid+256) >> 4,  bc1 = ((tid+256) & 15) << 2;

    FragC c0, c1;
    wmma::fill_fragment(c0, 0.0f);
    wmma::fill_fragment(c1, 0.0f);

    float4 pa0 = *(const float4*)(Abase + (size_t)ar0*Alds + ac0);
    float4 pa1 = *(const float4*)(Abase + (size_t)ar1*Alds + ac1);
    float4 pb0 = *(const float4*)(Bbase + (size_t)br0*G3 + bc0);
    float4 pb1 = *(const float4*)(Bbase + (size_t)br1*G3 + bc1);

    for (int kb = 0; kb < KLEN; kb += 32){
        *(float4*)(As + ar0*36 + ac0) = pa0;
        *(float4*)(As + ar1*36 + ac1) = pa1;
        *(float4*)(Bs + br0*68 + bc0) = pb0;
        *(float4*)(Bs + br1*68 + bc1) = pb1;
        __syncthreads();
        if (kb + 32 < KLEN){
            pa0 = *(const float4*)(Abase + (size_t)ar0*Alds + kb + 32 + ac0);
            pa1 = *(const float4*)(Abase + (size_t)ar1*Alds + kb + 32 + ac1);
            pb0 = *(const float4*)(Bbase + (size_t)(kb + 32 + br0)*G3 + bc0);
            pb1 = *(const float4*)(Bbase + (size_t)(kb + 32 + br1)*G3 + bc1);
        }
        const float* Ap = As + (wr*32)*36;
        const float* Bp = Bs + wc*16;
        #pragma unroll
        for (int ks = 0; ks < 32; ks += 8){
            FragA a0, a1; FragB b;
            wmma::load_matrix_sync(a0, Ap + ks, 36);
            wmma::load_matrix_sync(a1, Ap + 16*36 + ks, 36);
            wmma::load_matrix_sync(b, Bp + ks*68, 68);
            cvt_tf32_a(a0); cvt_tf32_a(a1); cvt_tf32_b(b);
            wmma::mma_sync(c0, a0, b, c0);
            wmma::mma_sync(c1, a1, b, c1);
        }
        __syncthreads();
    }
    float* Cs = SB;
    wmma::store_matrix_sync(Cs + (wr*32)*72 + wc*16, c0, 72, wmma::mem_row_major);
    wmma::store_matrix_sync(Cs + (wr*32 + 16)*72 + wc*16, c1, 72, wmma::mem_row_major);
}

// ---------------- fused gate GEMMs, both layers via blockIdx.z ----------------
// GATE=0 (zr): grid (8, 32, 2). A = g_Ahh rows (L0 K=256; L1 K=512 = [Ah0|Ah1])
// GATE=1 (c):  grid (4, 32, 2). A = g_Acc window (L0: cols 0:256 = Au0; L1: cols 256:768 = [Ah0|Au1])
template<int GATE>
__global__ void __launch_bounds__(256,2) gemm_gate(const float* __restrict__ Wh0,
                                                   const float* __restrict__ b1,
                                                   int t, int act0, int act1){
    __shared__ __align__(16) float SB[SBSZ];
    int L = blockIdx.z;
    if (L ? !act1 : !act0) return;
    int j0 = blockIdx.x << 6;
    int r0 = blockIdx.y << 6;
    int KL = L ? 512 : 256;
    int goff = GATE ? 512 : 0;

    const float* Abase;
    int Alds;
    if (GATE == 0){ Abase = g_Ahh + (size_t)r0*RS;                 Alds = RS; }
    else          { Abase = g_Acc + (size_t)r0*768 + (L ? 256:0);  Alds = 768; }
    const float* Bbase = (L ? (const float*)g_Wcat : Wh0) + goff + j0;

    cudaGridDependencySynchronize();
    mma_core(Abase, Alds, Bbase, KL, SB);
    __syncthreads();

    int tid = threadIdx.x;
    for (int e = tid; e < 64*64; e += 256){
        int lr = e >> 6, lc = e & 63;
        int r = r0 + lr;
        int j = j0 + lc;
        int q = r >> 8, n = r & 255;
        float add;
        if (L == 0) add = g_gx[(((size_t)(q*TT + t))*NN + n)*G3 + goff + j];
        else        add = b1[goff + j];
        float val = SB[lr*72 + lc] + add;
        size_t base = (size_t)r*RS + L*256;
        if (GATE == 0){
            float s = sigmoidf_(val);
            if (j < 256){
                g_zz[base + j] = s;
            } else {
                int j2 = j - 256;
                g_uu[base + j2] = s * g_hh[base + j2];
            }
        } else {
            float c = tanhf(val);
            size_t idx = base + j;
            float zv = g_zz[idx];
            float hn = zv * g_hh[idx] + (1.0f - zv) * c;
            g_hh[idx] = hn;
            if (L == 1)
                g_hseq[(((size_t)(q*TT + (t-1)))*NN + n)*HH + j] = hn;
        }
    }
    cudaTriggerProgrammaticLaunchCompletion();
}

// ---------------- output head ----------------
__global__ void out_head(const float* __restrict__ Wout, const float* __restrict__ bout,
                         float* __restrict__ out){
    __shared__ float sh[32*257];
    __shared__ float Ws[HH*DO];
    __shared__ float bs[DO];
    int r0 = blockIdx.x * 32;
    int tid = threadIdx.x;
    for (int i = tid; i < HH*DO; i += 256) Ws[i] = Wout[i];
    if (tid < DO) bs[tid] = bout[tid];
    const float4* H4 = (const float4*)g_hseq;
    for (int i = tid; i < 32*64; i += 256){
        int rr = i >> 6, c4 = i & 63;
        float4 v = H4[((size_t)(r0 + rr))*64 + c4];
        float* dst = &sh[rr*257 + c4*4];
        dst[0]=v.x; dst[1]=v.y; dst[2]=v.z; dst[3]=v.w;
    }
    __syncthreads();
    for (int oi = tid; oi < 32*DO; oi += 256){
        int rr = oi / DO, c = oi % DO;
        float a0 = bs[c], a1 = 0.0f;
        const float* sr = &sh[rr*257];
        for (int k = 0; k < HH; k += 2){
            a0 += sr[k]   * Ws[k*DO + c];
            a1 += sr[k+1] * Ws[(k+1)*DO + c];
        }
        out[(size_t)(r0 + rr)*DO + c] = a0 + a1;
    }
}

// ---------------- PDL launch helpers ----------------
static inline void pdl_conv(int which){
    cudaLaunchConfig_t cfg = {};
    cudaLaunchAttribute at[1];
    at[0].id = cudaLaunchAttributeProgrammaticStreamSerialization;
    at[0].val.programmaticStreamSerializationAllowed = 1;
    cfg.gridDim = dim3(2*BB*NN);
    cfg.blockDim = dim3(64);
    cfg.attrs = at;
    cfg.numAttrs = 1;
    cfg.stream = 0;
    cudaLaunchKernelEx(&cfg, conv_step, which);
}
template<int GATE>
static inline void pdl_gate(dim3 grid, const float* Wh0, const float* b1,
                            int t, int a0, int a1){
    cudaLaunchConfig_t cfg = {};
    cudaLaunchAttribute at[1];
    at[0].id = cudaLaunchAttributeProgrammaticStreamSerialization;
    at[0].val.programmaticStreamSerializationAllowed = 1;
    cfg.gridDim = grid;
    cfg.blockDim = dim3(256);
    cfg.attrs = at;
    cfg.numAttrs = 1;
    cfg.stream = 0;
    cudaLaunchKernelEx(&cfg, gemm_gate<GATE>, Wh0, b1, t, a0, a1);
}

// ---------------- launch: pipelined 2-layer recurrence, 65 super-steps ----------------
extern "C" void kernel_launch(void* const* d_in, const int* in_sizes, int n_in,
                              void* d_out, int out_size) {
    const float* x2d  = (const float*)d_in[0];
    const float* mask = (const float*)d_in[1];
    const float* adj  = (const float*)d_in[2];
    const float* Wx0  = (const float*)d_in[3];
    const float* Wh0  = (const float*)d_in[4];
    const float* b0   = (const float*)d_in[5];
    const float* Wx1  = (const float*)d_in[6];
    const float* Wh1  = (const float*)d_in[7];
    const float* b1   = (const float*)d_in[8];
    const float* Wout = (const float*)d_in[9];
    const float* bout = (const float*)d_in[10];
    float* out = (float*)d_out;

    build_csr<<<1, 256>>>(adj);
    prep_wcat<<<1536, 256>>>(Wx1, Wh1);
    prep_gx0<<<BB*TT, 256>>>(x2d, mask, Wx0, b0);
    zero_hh<<<1024, 256>>>();

    for (int t = 0; t <= TT; t++){
        int a0 = (t < TT) ? 1 : 0;
        int a1 = (t > 0) ? 1 : 0;
        pdl_conv(0);                                        // Ah0|Ah1 (+Acc copy)
        pdl_gate<0>(dim3(8, 32, 2), Wh0, b1, t, a0, a1);    // z,r,u both layers
        pdl_conv(1);                                        // Au0|Au1
        pdl_gate<1>(dim3(4, 32, 2), Wh0, b1, t, a0, a1);    // c + h update
    }

    out_head<<<(BB*TT*NN)/32, 256>>>(Wout, bout, out);
}